// round 3
// baseline (speedup 1.0000x reference)
#include <cuda_runtime.h>

// LoCon1d: out[b][o][s] = sum_{c,k} in[b][c][s+k-1] * w[o][c][s][k] + bias[o][s]
// B=16, Cin=64, Cout=64, S=1024, K=3 (zero pad)

#define S_LEN   1024
#define CIN     64
#define COUT    64
#define BATCH   16
#define KW      3
#define S_TILE  16
#define O_TILE  16
#define HALO    (S_TILE + 2)     // 18
#define THREADS 128
// shared: float4 entries, (c*HALO + j) rows of 5 float4 (4 used + 1 pad for banks)
#define ROW4    5
#define SH4_CNT (CIN * HALO * ROW4)          // 5760 float4
#define SMEM_BYTES (SH4_CNT * 16)            // 92160 B

typedef unsigned long long u64;

__device__ __forceinline__ u64 splat2(float w) {
    u64 r;
    asm("mov.b64 %0, {%1, %1};" : "=l"(r) : "f"(w));
    return r;
}
__device__ __forceinline__ void fma2(u64 &d, u64 a, u64 b) {
    asm("fma.rn.f32x2 %0, %1, %2, %0;" : "+l"(d) : "l"(a), "l"(b));
}
__device__ __forceinline__ float2 u2f(u64 u) {
    float2 r;
    asm("mov.b64 {%0, %1}, %2;" : "=f"(r.x), "=f"(r.y) : "l"(u));
    return r;
}

// pick component i (0..11) out of float4 w[3]; i is compile-time under unroll
#define WF(warr, i) (((i) & 3) == 0 ? (warr)[(i) >> 2].x : \
                     ((i) & 3) == 1 ? (warr)[(i) >> 2].y : \
                     ((i) & 3) == 2 ? (warr)[(i) >> 2].z : (warr)[(i) >> 2].w)

__global__ void __launch_bounds__(THREADS, 2)
locon1d_kernel(const float* __restrict__ input,
               const float* __restrict__ weight,
               const float* __restrict__ bias,
               float* __restrict__ out)
{
    extern __shared__ float4 sh4[];

    const int s0 = blockIdx.x * S_TILE;
    const int o0 = blockIdx.y * O_TILE;
    const int tid = threadIdx.x;

    // ---------------- fill input tile into shared -------------------------
    // logical m = (c*HALO + j)*4 + bq  ->  stored at  m + (m>>2)  (row stride 5)
    // entry = float4 over batches {4bq .. 4bq+3} of input[b][c][s0-1+j]
    for (int m = tid; m < CIN * HALO * 4; m += THREADS) {
        const int bq = m & 3;
        const int t  = m >> 2;
        const int j  = t % HALO;
        const int c  = t / HALO;
        const int s  = s0 - 1 + j;
        float4 v = make_float4(0.f, 0.f, 0.f, 0.f);
        if ((unsigned)s < (unsigned)S_LEN) {
            const float* p = input + ((size_t)(4 * bq) * CIN + c) * S_LEN + s;
            v.x = p[0];
            v.y = p[(size_t)CIN * S_LEN];
            v.z = p[2 * (size_t)CIN * S_LEN];
            v.w = p[3 * (size_t)CIN * S_LEN];
        }
        sh4[m + (m >> 2)] = v;
    }
    __syncthreads();

    // ---------------- thread mapping --------------------------------------
    const int o_l = tid >> 4;          // 0..7
    const int sg  = (tid >> 2) & 3;    // 0..3  (4 s each)
    const int bg  = tid & 3;           // 0..3  (4 b each)
    const int oA = o0 + o_l;
    const int oB = o0 + o_l + 8;
    const int sbase = s0 + sg * 4;
    const int jbase = sg * 4;

    const ulonglong2* shp2 = reinterpret_cast<const ulonglong2*>(sh4);
    const int svb = ROW4 * jbase + bg;  // float4-index offset (per c add 90)

    // weight float4 base pointers; per-c stride = 1024*3/4 = 768 float4
    const float4* wpA = reinterpret_cast<const float4*>(weight) +
                        (((size_t)oA * CIN) * S_LEN * 3 + (size_t)sbase * 3) / 4;
    const float4* wpB = reinterpret_cast<const float4*>(weight) +
                        (((size_t)oB * CIN) * S_LEN * 3 + (size_t)sbase * 3) / 4;

    u64 acc[2][4][2];
    #pragma unroll
    for (int i = 0; i < 2; ++i)
        #pragma unroll
        for (int j = 0; j < 4; ++j) { acc[i][j][0] = 0ull; acc[i][j][1] = 0ull; }

    float4 wa[4][3], wb[4][3];     // 4-deep weight prefetch ring
    ulonglong2 v[2][6];            // 2-deep input prefetch

    auto WLOAD = [&](int c) {
        const float4* pa = wpA + (size_t)c * 768;
        const float4* pb = wpB + (size_t)c * 768;
        #pragma unroll
        for (int i = 0; i < 3; ++i) {
            wa[c & 3][i] = __ldcs(pa + i);
            wb[c & 3][i] = __ldcs(pb + i);
        }
    };
    auto VLOAD = [&](int c) {
        const int base = 90 * c + svb;
        #pragma unroll
        for (int d = 0; d < 6; ++d)
            v[c & 1][d] = shp2[base + ROW4 * d];
    };

    WLOAD(0); WLOAD(1); WLOAD(2); WLOAD(3);
    VLOAD(0);

    #pragma unroll 4
    for (int c = 0; c < CIN; ++c) {
        if (c + 1 < CIN) VLOAD(c + 1);      // writes v[(c+1)&1] — other slot, safe
        const int cb = c & 1;
        const int wq = c & 3;
        #pragma unroll
        for (int ss = 0; ss < 4; ++ss) {
            #pragma unroll
            for (int k = 0; k < KW; ++k) {
                const int d  = ss + k;          // 0..5
                const int wi = ss * 3 + k;      // 0..11
                const u64 lo = v[cb][d].x;
                const u64 hi = v[cb][d].y;
                const u64 sa = splat2(WF(wa[wq], wi));
                fma2(acc[0][ss][0], lo, sa);
                fma2(acc[0][ss][1], hi, sa);
                const u64 sb = splat2(WF(wb[wq], wi));
                fma2(acc[1][ss][0], lo, sb);
                fma2(acc[1][ss][1], hi, sb);
            }
        }
        // Prefetch AFTER compute: WLOAD(c+4) writes wa[(c+4)&3] == wa[c&3],
        // which the FMA block above just finished reading. Issuing it here
        // (register dep enforces order) fixes the R2 clobber; consumption is
        // 4 iterations away, so latency is still fully covered.
        if (c + 4 < CIN) WLOAD(c + 4);
    }

    // ---------------- epilogue: bias + store -------------------------------
    #pragma unroll
    for (int o2 = 0; o2 < 2; ++o2) {
        const int o = o2 ? oB : oA;
        const float4 bz = *reinterpret_cast<const float4*>(bias + (size_t)o * S_LEN + sbase);
        #pragma unroll
        for (int pr = 0; pr < 2; ++pr) {
            const float2 f0 = u2f(acc[o2][0][pr]);
            const float2 f1 = u2f(acc[o2][1][pr]);
            const float2 f2 = u2f(acc[o2][2][pr]);
            const float2 f3 = u2f(acc[o2][3][pr]);
            const int b0 = bg * 4 + pr * 2;
            float4 r0 = make_float4(f0.x + bz.x, f1.x + bz.y, f2.x + bz.z, f3.x + bz.w);
            float4 r1 = make_float4(f0.y + bz.x, f1.y + bz.y, f2.y + bz.z, f3.y + bz.w);
            *reinterpret_cast<float4*>(out + ((size_t)(b0 * COUT + o)) * S_LEN + sbase) = r0;
            *reinterpret_cast<float4*>(out + ((size_t)((b0 + 1) * COUT + o)) * S_LEN + sbase) = r1;
        }
    }
}

extern "C" void kernel_launch(void* const* d_in, const int* in_sizes, int n_in,
                              void* d_out, int out_size) {
    const float* input  = (const float*)d_in[0];
    const float* weight = (const float*)d_in[1];
    const float* bias   = (const float*)d_in[2];
    float* out = (float*)d_out;

    cudaFuncSetAttribute(locon1d_kernel,
                         cudaFuncAttributeMaxDynamicSharedMemorySize, SMEM_BYTES);

    dim3 grid(S_LEN / S_TILE, COUT / O_TILE);   // (64, 4)
    locon1d_kernel<<<grid, THREADS, SMEM_BYTES>>>(input, weight, bias, out);
}